// round 1
// baseline (speedup 1.0000x reference)
#include <cuda_runtime.h>
#include <cstdint>

// Problem constants (fixed by the dataset)
#define NNODES 50000
#define FIN    128
#define HDIM   128
#define FOUTD  64
#define NEDGES 800000

// ---------------- scratch (device globals; no allocation allowed) -------------
__device__ float g_h1  [NNODES * HDIM];   // x @ W1
__device__ float g_agg1[NNODES * HDIM];   // aggregated conv1 (then z1 in place)
__device__ float g_h2  [NNODES * FOUTD];  // z1 @ W2
__device__ float g_agg2[NNODES * FOUTD];  // aggregated conv2
__device__ float g_dinv[NNODES];
__device__ int   g_deg [NNODES];

// ---------------- degree / norm ----------------------------------------------
__global__ void k_init_deg(int n) {
    int i = blockIdx.x * blockDim.x + threadIdx.x;
    if (i < n) g_deg[i] = 1;                 // self-loop
}

__global__ void k_count(const int* __restrict__ ei, int e) {
    int i = blockIdx.x * blockDim.x + threadIdx.x;
    if (i < e) atomicAdd(&g_deg[ei[e + i]], 1);   // dst = ei[E + i]
}

__global__ void k_dinv(int n) {
    int i = blockIdx.x * blockDim.x + threadIdx.x;
    if (i < n) g_dinv[i] = rsqrtf((float)g_deg[i]);
}

// ---------------- GEMM: Y[n,COLS] = X[n,128] @ W[128,COLS] -------------------
// Block tile: 64 rows x COLS cols, 256 threads (16x16), thread tile 4 x COLS/16.
// Xs stored transposed [k][row] with pad 65 for conflict-free LDS.
template<int COLS>
__global__ void k_gemm(const float* __restrict__ X, const float* __restrict__ W,
                       float* __restrict__ Y, int n)
{
    extern __shared__ float sm[];
    float* Xs = sm;                 // 128 * 65
    float* Ws = sm + 128 * 65;      // 128 * COLS

    const int tid = threadIdx.x;
    const int tx  = tid & 15;
    const int ty  = tid >> 4;
    const int row0 = blockIdx.x * 64;
    constexpr int CPT = COLS / 16;

    // load W (row-major [k][c]) fully into smem
    for (int idx = tid; idx < 128 * COLS; idx += 256) Ws[idx] = W[idx];

    // load X tile transposed: Xs[k*65 + r] = X[(row0+r)*128 + k]
    for (int idx = tid; idx < 64 * 128; idx += 256) {
        int r = idx >> 7, k = idx & 127;
        float v = (row0 + r < n) ? X[(size_t)(row0 + r) * 128 + k] : 0.0f;
        Xs[k * 65 + r] = v;
    }
    __syncthreads();

    float acc[4][CPT];
    #pragma unroll
    for (int i = 0; i < 4; i++)
        #pragma unroll
        for (int j = 0; j < CPT; j++) acc[i][j] = 0.0f;

    #pragma unroll 8
    for (int k = 0; k < 128; k++) {
        float xr[4];
        #pragma unroll
        for (int i = 0; i < 4; i++) xr[i] = Xs[k * 65 + ty * 4 + i];
        float wr[CPT];
        #pragma unroll
        for (int j = 0; j < CPT; j++) wr[j] = Ws[k * COLS + tx + 16 * j];
        #pragma unroll
        for (int i = 0; i < 4; i++)
            #pragma unroll
            for (int j = 0; j < CPT; j++) acc[i][j] = fmaf(xr[i], wr[j], acc[i][j]);
    }

    #pragma unroll
    for (int i = 0; i < 4; i++) {
        int row = row0 + ty * 4 + i;
        if (row < n) {
            #pragma unroll
            for (int j = 0; j < CPT; j++)
                Y[(size_t)row * COLS + tx + 16 * j] = acc[i][j];
        }
    }
}

// ---------------- self-loop init: agg[i][c] = h[i][c] * dinv[i]^2 ------------
template<int C>
__global__ void k_self(const float* __restrict__ h, float* __restrict__ agg, int n)
{
    int idx = blockIdx.x * blockDim.x + threadIdx.x;
    if (idx < n * C) {
        int i = idx / C;
        float di = g_dinv[i];
        agg[idx] = h[idx] * di * di;
    }
}

// ---------------- edge scatter (warp per edge) --------------------------------
__global__ void k_scatter128(const int* __restrict__ ei,
                             const float* __restrict__ h,
                             float* __restrict__ agg, int e)
{
    int g    = blockIdx.x * blockDim.x + threadIdx.x;
    int w    = g >> 5;
    int lane = g & 31;
    if (w >= e) return;
    int s = ei[w];
    int d = ei[e + w];
    float nrm = g_dinv[s] * g_dinv[d];
    float4 v = ((const float4*)(h + (size_t)s * 128))[lane];
    float* dst = agg + (size_t)d * 128 + lane * 4;
    atomicAdd(dst + 0, v.x * nrm);
    atomicAdd(dst + 1, v.y * nrm);
    atomicAdd(dst + 2, v.z * nrm);
    atomicAdd(dst + 3, v.w * nrm);
}

__global__ void k_scatter64(const int* __restrict__ ei,
                            const float* __restrict__ h,
                            float* __restrict__ agg, int e)
{
    int g    = blockIdx.x * blockDim.x + threadIdx.x;
    int w    = g >> 5;
    int lane = g & 31;
    if (w >= e) return;
    int s = ei[w];
    int d = ei[e + w];
    float nrm = g_dinv[s] * g_dinv[d];
    float2 v = ((const float2*)(h + (size_t)s * 64))[lane];
    float* dst = agg + (size_t)d * 64 + lane * 2;
    atomicAdd(dst + 0, v.x * nrm);
    atomicAdd(dst + 1, v.y * nrm);
}

// ---------------- bias + PReLU -------------------------------------------------
template<int C>
__global__ void k_fin_inplace(float* __restrict__ io, const float* __restrict__ b,
                              const float* __restrict__ pa, int n)
{
    int idx = blockIdx.x * blockDim.x + threadIdx.x;
    if (idx < n * C) {
        float v = io[idx] + b[idx & (C - 1)];
        float a = *pa;
        io[idx] = (v >= 0.0f) ? v : a * v;
    }
}

template<int C>
__global__ void k_fin_out(const float* __restrict__ agg, const float* __restrict__ b,
                          const float* __restrict__ pa, float* __restrict__ out, int n)
{
    int idx = blockIdx.x * blockDim.x + threadIdx.x;
    if (idx < n * C) {
        float v = agg[idx] + b[idx & (C - 1)];
        float a = *pa;
        out[idx] = (v >= 0.0f) ? v : a * v;
    }
}

// ---------------- launch -------------------------------------------------------
extern "C" void kernel_launch(void* const* d_in, const int* in_sizes, int n_in,
                              void* d_out, int out_size)
{
    const float* x   = (const float*)d_in[0];
    const int*   ei  = (const int*)  d_in[1];
    const float* W1  = (const float*)d_in[2];
    const float* b1  = (const float*)d_in[3];
    const float* W2  = (const float*)d_in[4];
    const float* b2  = (const float*)d_in[5];
    const float* pa  = (const float*)d_in[6];
    float* out = (float*)d_out;

    const int n = in_sizes[0] / FIN;     // 50000
    const int e = in_sizes[1] / 2;       // 800000

    // dynamic smem sizes for the two GEMM instantiations
    const int smem1 = (128 * 65 + 128 * HDIM)  * sizeof(float);  // ~96.5 KB
    const int smem2 = (128 * 65 + 128 * FOUTD) * sizeof(float);  // ~64.5 KB
    cudaFuncSetAttribute(k_gemm<HDIM>,  cudaFuncAttributeMaxDynamicSharedMemorySize, smem1);
    cudaFuncSetAttribute(k_gemm<FOUTD>, cudaFuncAttributeMaxDynamicSharedMemorySize, smem2);

    const int T = 256;
    float* h1   = nullptr; cudaGetSymbolAddress((void**)&h1,   g_h1);
    float* agg1 = nullptr; cudaGetSymbolAddress((void**)&agg1, g_agg1);
    float* h2   = nullptr; cudaGetSymbolAddress((void**)&h2,   g_h2);
    float* agg2 = nullptr; cudaGetSymbolAddress((void**)&agg2, g_agg2);

    // 1) degrees + norm
    k_init_deg<<<(n + T - 1) / T, T>>>(n);
    k_count   <<<(e + T - 1) / T, T>>>(ei, e);
    k_dinv    <<<(n + T - 1) / T, T>>>(n);

    // 2) conv1
    k_gemm<HDIM><<<(n + 63) / 64, 256, smem1>>>(x, W1, h1, n);
    k_self<HDIM><<<(n * HDIM + T - 1) / T, T>>>(h1, agg1, n);
    {
        long long threads = (long long)e * 32;
        k_scatter128<<<(int)((threads + T - 1) / T), T>>>(ei, h1, agg1, e);
    }
    k_fin_inplace<HDIM><<<(n * HDIM + T - 1) / T, T>>>(agg1, b1, pa, n);

    // 3) conv2
    k_gemm<FOUTD><<<(n + 63) / 64, 256, smem2>>>(agg1, W2, h2, n);
    k_self<FOUTD><<<(n * FOUTD + T - 1) / T, T>>>(h2, agg2, n);
    {
        long long threads = (long long)e * 32;
        k_scatter64<<<(int)((threads + T - 1) / T), T>>>(ei, h2, agg2, e);
    }
    k_fin_out<FOUTD><<<(n * FOUTD + T - 1) / T, T>>>(agg2, b2, pa, out, n);
}

// round 2
// speedup vs baseline: 1.7483x; 1.7483x over previous
#include <cuda_runtime.h>
#include <cstdint>

// Problem constants (fixed by the dataset)
#define NNODES 50000
#define FIN    128
#define HDIM   128
#define FOUTD  64
#define NEDGES 800000

// ---------------- scratch (device globals; no allocation allowed) -------------
__device__ float g_h1  [NNODES * HDIM];    // x @ W1
__device__ float g_z1  [NNODES * HDIM];    // prelu(agg1 + b1)  (input to GEMM2)
__device__ float g_h2  [NNODES * FOUTD];   // z1 @ W2
__device__ float g_dinv[NNODES];
__device__ int   g_deg [NNODES];           // in-degree WITHOUT self loop
__device__ int   g_rowptr[NNODES + 1];
__device__ int   g_cursor[NNODES];
__device__ int2  g_adj [NEDGES];           // (src, norm-as-bits) sorted by dst

// ---------------- degree / norm ----------------------------------------------
__global__ void k_zero_deg(int n) {
    int i = blockIdx.x * blockDim.x + threadIdx.x;
    if (i < n) g_deg[i] = 0;
}

__global__ void k_count(const int* __restrict__ ei, int e) {
    int i = blockIdx.x * blockDim.x + threadIdx.x;
    if (i < e) atomicAdd(&g_deg[ei[e + i]], 1);   // dst = ei[E + i]
}

__global__ void k_dinv(int n) {
    int i = blockIdx.x * blockDim.x + threadIdx.x;
    if (i < n) g_dinv[i] = rsqrtf((float)(g_deg[i] + 1));  // + self loop
}

// ---------------- exclusive scan of g_deg -> g_rowptr / g_cursor --------------
// Single block, 1024 threads, each owns a contiguous chunk.
__global__ void k_scan(int n) {
    __shared__ int ssum[1024];
    const int tid = threadIdx.x;
    const int per = (n + 1023) / 1024;
    const int beg = min(tid * per, n);
    const int end = min(beg + per, n);

    int s = 0;
    for (int i = beg; i < end; i++) s += g_deg[i];
    ssum[tid] = s;
    __syncthreads();

    // inclusive scan over ssum (Hillis-Steele)
    for (int off = 1; off < 1024; off <<= 1) {
        int v = (tid >= off) ? ssum[tid - off] : 0;
        __syncthreads();
        ssum[tid] += v;
        __syncthreads();
    }

    int run = (tid > 0) ? ssum[tid - 1] : 0;
    for (int i = beg; i < end; i++) {
        int d = g_deg[i];
        g_rowptr[i] = run;
        g_cursor[i] = run;
        run += d;
    }
    if (end == n && beg < n) g_rowptr[n] = run;
    if (n == 0 && tid == 0)  g_rowptr[0] = 0;
}

// ---------------- bucket fill: adj records sorted by dst ----------------------
__global__ void k_fill(const int* __restrict__ ei, int e) {
    int i = blockIdx.x * blockDim.x + threadIdx.x;
    if (i >= e) return;
    int s = ei[i];
    int d = ei[e + i];
    float nrm = g_dinv[s] * g_dinv[d];
    int pos = atomicAdd(&g_cursor[d], 1);
    g_adj[pos] = make_int2(s, __float_as_int(nrm));
}

// ---------------- GEMM: Y[n,COLS] = X[n,128] @ W[128,COLS] -------------------
template<int COLS>
__global__ void k_gemm(const float* __restrict__ X, const float* __restrict__ W,
                       float* __restrict__ Y, int n)
{
    extern __shared__ float sm[];
    float* Xs = sm;                 // 128 * 65
    float* Ws = sm + 128 * 65;      // 128 * COLS

    const int tid = threadIdx.x;
    const int tx  = tid & 15;
    const int ty  = tid >> 4;
    const int row0 = blockIdx.x * 64;
    constexpr int CPT = COLS / 16;

    for (int idx = tid; idx < 128 * COLS; idx += 256) Ws[idx] = W[idx];

    for (int idx = tid; idx < 64 * 128; idx += 256) {
        int r = idx >> 7, k = idx & 127;
        float v = (row0 + r < n) ? X[(size_t)(row0 + r) * 128 + k] : 0.0f;
        Xs[k * 65 + r] = v;
    }
    __syncthreads();

    float acc[4][CPT];
    #pragma unroll
    for (int i = 0; i < 4; i++)
        #pragma unroll
        for (int j = 0; j < CPT; j++) acc[i][j] = 0.0f;

    #pragma unroll 8
    for (int k = 0; k < 128; k++) {
        float xr[4];
        #pragma unroll
        for (int i = 0; i < 4; i++) xr[i] = Xs[k * 65 + ty * 4 + i];
        float wr[CPT];
        #pragma unroll
        for (int j = 0; j < CPT; j++) wr[j] = Ws[k * COLS + tx + 16 * j];
        #pragma unroll
        for (int i = 0; i < 4; i++)
            #pragma unroll
            for (int j = 0; j < CPT; j++) acc[i][j] = fmaf(xr[i], wr[j], acc[i][j]);
    }

    #pragma unroll
    for (int i = 0; i < 4; i++) {
        int row = row0 + ty * 4 + i;
        if (row < n) {
            #pragma unroll
            for (int j = 0; j < CPT; j++)
                Y[(size_t)row * COLS + tx + 16 * j] = acc[i][j];
        }
    }
}

// ---------------- gather (warp per dst node) + bias + PReLU -------------------
// C = 128: each lane owns a float4 (32*4 = 128 cols)
__global__ void k_gather128(const float* __restrict__ h,
                            const float* __restrict__ b,
                            const float* __restrict__ pa,
                            float* __restrict__ out, int n)
{
    int g    = blockIdx.x * blockDim.x + threadIdx.x;
    int node = g >> 5;
    int lane = g & 31;
    if (node >= n) return;

    const float4* hv = (const float4*)h;

    // self loop: h[node] * dinv^2
    float di = g_dinv[node];
    float sw = di * di;
    float4 acc = hv[(size_t)node * 32 + lane];
    acc.x *= sw; acc.y *= sw; acc.z *= sw; acc.w *= sw;

    int e0 = g_rowptr[node];
    int e1 = g_rowptr[node + 1];
    for (int e = e0; e < e1; e++) {
        int2 rec = __ldg(&g_adj[e]);
        float w  = __int_as_float(rec.y);
        float4 v = hv[(size_t)rec.x * 32 + lane];
        acc.x = fmaf(v.x, w, acc.x);
        acc.y = fmaf(v.y, w, acc.y);
        acc.z = fmaf(v.z, w, acc.z);
        acc.w = fmaf(v.w, w, acc.w);
    }

    float a = *pa;
    float4 bb = ((const float4*)b)[lane];
    acc.x += bb.x; acc.y += bb.y; acc.z += bb.z; acc.w += bb.w;
    acc.x = (acc.x >= 0.0f) ? acc.x : a * acc.x;
    acc.y = (acc.y >= 0.0f) ? acc.y : a * acc.y;
    acc.z = (acc.z >= 0.0f) ? acc.z : a * acc.z;
    acc.w = (acc.w >= 0.0f) ? acc.w : a * acc.w;

    ((float4*)out)[(size_t)node * 32 + lane] = acc;
}

// C = 64: each lane owns a float2
__global__ void k_gather64(const float* __restrict__ h,
                           const float* __restrict__ b,
                           const float* __restrict__ pa,
                           float* __restrict__ out, int n)
{
    int g    = blockIdx.x * blockDim.x + threadIdx.x;
    int node = g >> 5;
    int lane = g & 31;
    if (node >= n) return;

    const float2* hv = (const float2*)h;

    float di = g_dinv[node];
    float sw = di * di;
    float2 acc = hv[(size_t)node * 32 + lane];
    acc.x *= sw; acc.y *= sw;

    int e0 = g_rowptr[node];
    int e1 = g_rowptr[node + 1];
    for (int e = e0; e < e1; e++) {
        int2 rec = __ldg(&g_adj[e]);
        float w  = __int_as_float(rec.y);
        float2 v = hv[(size_t)rec.x * 32 + lane];
        acc.x = fmaf(v.x, w, acc.x);
        acc.y = fmaf(v.y, w, acc.y);
    }

    float a = *pa;
    float2 bb = ((const float2*)b)[lane];
    acc.x += bb.x; acc.y += bb.y;
    acc.x = (acc.x >= 0.0f) ? acc.x : a * acc.x;
    acc.y = (acc.y >= 0.0f) ? acc.y : a * acc.y;

    ((float2*)out)[(size_t)node * 32 + lane] = acc;
}

// ---------------- launch -------------------------------------------------------
extern "C" void kernel_launch(void* const* d_in, const int* in_sizes, int n_in,
                              void* d_out, int out_size)
{
    const float* x   = (const float*)d_in[0];
    const int*   ei  = (const int*)  d_in[1];
    const float* W1  = (const float*)d_in[2];
    const float* b1  = (const float*)d_in[3];
    const float* W2  = (const float*)d_in[4];
    const float* b2  = (const float*)d_in[5];
    const float* pa  = (const float*)d_in[6];
    float* out = (float*)d_out;

    const int n = in_sizes[0] / FIN;     // 50000
    const int e = in_sizes[1] / 2;       // 800000

    const int smem1 = (128 * 65 + 128 * HDIM)  * sizeof(float);
    const int smem2 = (128 * 65 + 128 * FOUTD) * sizeof(float);
    cudaFuncSetAttribute(k_gemm<HDIM>,  cudaFuncAttributeMaxDynamicSharedMemorySize, smem1);
    cudaFuncSetAttribute(k_gemm<FOUTD>, cudaFuncAttributeMaxDynamicSharedMemorySize, smem2);

    const int T = 256;
    float* h1 = nullptr; cudaGetSymbolAddress((void**)&h1, g_h1);
    float* z1 = nullptr; cudaGetSymbolAddress((void**)&z1, g_z1);
    float* h2 = nullptr; cudaGetSymbolAddress((void**)&h2, g_h2);

    // 1) CSR build
    k_zero_deg<<<(n + T - 1) / T, T>>>(n);
    k_count   <<<(e + T - 1) / T, T>>>(ei, e);
    k_dinv    <<<(n + T - 1) / T, T>>>(n);
    k_scan    <<<1, 1024>>>(n);
    k_fill    <<<(e + T - 1) / T, T>>>(ei, e);

    // 2) conv1: GEMM + gather(+bias+PReLU)
    k_gemm<HDIM><<<(n + 63) / 64, 256, smem1>>>(x, W1, h1, n);
    {
        long long threads = (long long)n * 32;
        k_gather128<<<(int)((threads + T - 1) / T), T>>>(h1, b1, pa, z1, n);
    }

    // 3) conv2: GEMM + gather(+bias+PReLU) -> out
    k_gemm<FOUTD><<<(n + 63) / 64, 256, smem2>>>(z1, W2, h2, n);
    {
        long long threads = (long long)n * 32;
        k_gather64<<<(int)((threads + T - 1) / T), T>>>(h2, b2, pa, out, n);
    }
}

// round 3
// speedup vs baseline: 2.1150x; 1.2097x over previous
#include <cuda_runtime.h>
#include <cstdint>

// Problem constants (fixed by the dataset)
#define NNODES 50000
#define FIN    128
#define HDIM   128
#define FOUTD  64
#define NEDGES 800000

// ---------------- scratch (device globals; no allocation allowed) -------------
__device__ float g_h1  [NNODES * HDIM];    // x @ W1
__device__ float g_z1  [NNODES * HDIM];    // prelu(agg1 + b1)
__device__ float g_h2  [NNODES * FOUTD];   // z1 @ W2
__device__ float g_dinv[NNODES];
__device__ int   g_deg [NNODES];
__device__ int   g_rowptr[NNODES + 1];
__device__ int   g_cursor[NNODES];
__device__ int2  g_adj [NEDGES];
__device__ int   g_bsum[256];
__device__ int   g_boff[256];

// ---------------- degree / norm ----------------------------------------------
__global__ void k_zero_deg(int n) {
    int i = blockIdx.x * blockDim.x + threadIdx.x;
    if (i < n) g_deg[i] = 0;
}

__global__ void k_count(const int* __restrict__ ei, int e) {
    int i = blockIdx.x * blockDim.x + threadIdx.x;
    if (i < e) atomicAdd(&g_deg[ei[e + i]], 1);
}

__global__ void k_dinv(int n) {
    int i = blockIdx.x * blockDim.x + threadIdx.x;
    if (i < n) g_dinv[i] = rsqrtf((float)(g_deg[i] + 1));  // + self loop
}

// ---------------- parallel exclusive scan (3 phases) --------------------------
// Phase 1: per-block (256 elems) exclusive scan -> rowptr (local), block sums
__global__ void k_scan_blk(int n) {
    __shared__ int wsum[8];
    const int tid  = threadIdx.x;
    const int i    = blockIdx.x * 256 + tid;
    const int lane = tid & 31, wid = tid >> 5;

    int v = (i < n) ? g_deg[i] : 0;
    int x = v;
    #pragma unroll
    for (int off = 1; off < 32; off <<= 1) {
        int y = __shfl_up_sync(0xffffffffu, x, off);
        if (lane >= off) x += y;
    }
    if (lane == 31) wsum[wid] = x;
    __syncthreads();
    if (wid == 0) {
        int w = (lane < 8) ? wsum[lane] : 0;
        #pragma unroll
        for (int off = 1; off < 8; off <<= 1) {
            int y = __shfl_up_sync(0xffffffffu, w, off);
            if (lane >= off) w += y;
        }
        if (lane < 8) wsum[lane] = w;
    }
    __syncthreads();
    int base = (wid > 0) ? wsum[wid - 1] : 0;
    if (i < n) g_rowptr[i] = base + x - v;           // exclusive, block-local
    if (tid == 255) g_bsum[blockIdx.x] = base + x;   // block total
}

// Phase 2: single block scans the (<=256) block sums -> g_boff, total -> rowptr[n]
__global__ void k_scan_mid(int nb, int n) {
    __shared__ int wsum[8];
    const int tid  = threadIdx.x;
    const int lane = tid & 31, wid = tid >> 5;

    int v = (tid < nb) ? g_bsum[tid] : 0;
    int x = v;
    #pragma unroll
    for (int off = 1; off < 32; off <<= 1) {
        int y = __shfl_up_sync(0xffffffffu, x, off);
        if (lane >= off) x += y;
    }
    if (lane == 31) wsum[wid] = x;
    __syncthreads();
    if (wid == 0) {
        int w = (lane < 8) ? wsum[lane] : 0;
        #pragma unroll
        for (int off = 1; off < 8; off <<= 1) {
            int y = __shfl_up_sync(0xffffffffu, w, off);
            if (lane >= off) w += y;
        }
        if (lane < 8) wsum[lane] = w;
    }
    __syncthreads();
    int base = (wid > 0) ? wsum[wid - 1] : 0;
    g_boff[tid] = base + x - v;
    if (tid == 255) g_rowptr[n] = base + x;  // grand total
}

// Phase 3: add block offsets, init cursors
__global__ void k_scan_add(int n) {
    int i = blockIdx.x * 256 + threadIdx.x;
    if (i < n) {
        int v = g_rowptr[i] + g_boff[blockIdx.x];
        g_rowptr[i] = v;
        g_cursor[i] = v;
    }
}

// ---------------- bucket fill: adj records sorted by dst ----------------------
__global__ void k_fill(const int* __restrict__ ei, int e) {
    int i = blockIdx.x * blockDim.x + threadIdx.x;
    if (i >= e) return;
    int s = ei[i];
    int d = ei[e + i];
    float nrm = g_dinv[s] * g_dinv[d];
    int pos = atomicAdd(&g_cursor[d], 1);
    g_adj[pos] = make_int2(s, __float_as_int(nrm));
}

// ---------------- tf32 tensor-core GEMM: Y[n,COLS] = X[n,128] @ W[128,COLS] ---
__device__ __forceinline__ uint32_t f2tf(float f) {
    uint32_t r;
    asm("cvt.rna.tf32.f32 %0, %1;" : "=r"(r) : "f"(f));
    return r;
}

template<int COLS>
__global__ void k_gemm_tc(const float* __restrict__ X, const float* __restrict__ W,
                          float* __restrict__ Y, int n)
{
    constexpr int XS = 132;          // Xs row stride (K=128 + pad 4)
    constexpr int WS = COLS + 8;     // Ws row stride (pad ≡ 8 mod 32)
    constexpr int MW = (COLS == 128) ? 2 : 4;   // warps along M
    constexpr int NW = 8 / MW;                  // warps along N
    constexpr int WM = 128 / MW;                // warp tile M
    constexpr int WN = COLS / NW;               // warp tile N (=32)
    constexpr int MF = WM / 16;
    constexpr int NF = WN / 8;                  // =4

    extern __shared__ uint32_t sm[];
    uint32_t* Xs = sm;                // [128 rows][XS]
    uint32_t* Ws = sm + 128 * XS;     // [128 k][WS]

    const int tid  = threadIdx.x;
    const int row0 = blockIdx.x * 128;

    // Load X tile (fp32 -> tf32), row-major [row][k]
    const float4* Xv = (const float4*)X;
    for (int idx = tid; idx < 128 * 32; idx += 256) {
        int r = idx >> 5, kq = idx & 31;
        float4 v = make_float4(0.f, 0.f, 0.f, 0.f);
        if (row0 + r < n) v = Xv[(size_t)(row0 + r) * 32 + kq];
        uint32_t* p = &Xs[r * XS + kq * 4];
        p[0] = f2tf(v.x); p[1] = f2tf(v.y); p[2] = f2tf(v.z); p[3] = f2tf(v.w);
    }
    // Load W (fp32 -> tf32), row-major [k][col]
    const float4* Wv = (const float4*)W;
    for (int idx = tid; idx < 128 * (COLS / 4); idx += 256) {
        int k = idx / (COLS / 4), nq = idx % (COLS / 4);
        float4 v = Wv[k * (COLS / 4) + nq];
        uint32_t* p = &Ws[k * WS + nq * 4];
        p[0] = f2tf(v.x); p[1] = f2tf(v.y); p[2] = f2tf(v.z); p[3] = f2tf(v.w);
    }
    __syncthreads();

    const int w    = tid >> 5;
    const int lane = tid & 31;
    const int mw   = w % MW, nw = w / MW;
    const int g    = lane >> 2, t = lane & 3;

    float acc[MF][NF][4];
    #pragma unroll
    for (int mf = 0; mf < MF; mf++)
        #pragma unroll
        for (int nf = 0; nf < NF; nf++)
            #pragma unroll
            for (int q = 0; q < 4; q++) acc[mf][nf][q] = 0.0f;

    for (int k0 = 0; k0 < 128; k0 += 8) {
        uint32_t b[NF][2];
        #pragma unroll
        for (int nf = 0; nf < NF; nf++) {
            int n0 = nw * WN + nf * 8;
            b[nf][0] = Ws[(k0 + t)     * WS + n0 + g];
            b[nf][1] = Ws[(k0 + 4 + t) * WS + n0 + g];
        }
        uint32_t a[MF][4];
        #pragma unroll
        for (int mf = 0; mf < MF; mf++) {
            int r = mw * WM + mf * 16;
            const uint32_t* xlo = &Xs[(r + g)     * XS + k0 + t];
            const uint32_t* xhi = &Xs[(r + 8 + g) * XS + k0 + t];
            a[mf][0] = xlo[0];
            a[mf][1] = xhi[0];
            a[mf][2] = xlo[4];
            a[mf][3] = xhi[4];
        }
        #pragma unroll
        for (int mf = 0; mf < MF; mf++)
            #pragma unroll
            for (int nf = 0; nf < NF; nf++)
                asm volatile(
                    "mma.sync.aligned.m16n8k8.row.col.f32.tf32.tf32.f32 "
                    "{%0,%1,%2,%3}, {%4,%5,%6,%7}, {%8,%9}, {%0,%1,%2,%3};\n"
                    : "+f"(acc[mf][nf][0]), "+f"(acc[mf][nf][1]),
                      "+f"(acc[mf][nf][2]), "+f"(acc[mf][nf][3])
                    : "r"(a[mf][0]), "r"(a[mf][1]), "r"(a[mf][2]), "r"(a[mf][3]),
                      "r"(b[nf][0]), "r"(b[nf][1]));
    }

    // Epilogue: c0,c1 at (row=g, col=2t,2t+1); c2,c3 at row=g+8
    #pragma unroll
    for (int mf = 0; mf < MF; mf++) {
        int r_lo = row0 + mw * WM + mf * 16 + g;
        int r_hi = r_lo + 8;
        #pragma unroll
        for (int nf = 0; nf < NF; nf++) {
            int c = nw * WN + nf * 8 + 2 * t;
            if (r_lo < n) {
                float2 v = make_float2(acc[mf][nf][0], acc[mf][nf][1]);
                *(float2*)&Y[(size_t)r_lo * COLS + c] = v;
            }
            if (r_hi < n) {
                float2 v = make_float2(acc[mf][nf][2], acc[mf][nf][3]);
                *(float2*)&Y[(size_t)r_hi * COLS + c] = v;
            }
        }
    }
}

// ---------------- gather (warp per dst node) + bias + PReLU -------------------
__global__ void k_gather128(const float* __restrict__ h,
                            const float* __restrict__ b,
                            const float* __restrict__ pa,
                            float* __restrict__ out, int n)
{
    int g    = blockIdx.x * blockDim.x + threadIdx.x;
    int node = g >> 5;
    int lane = g & 31;
    if (node >= n) return;

    const float4* hv = (const float4*)h;

    float di = g_dinv[node];
    float sw = di * di;
    float4 acc = hv[(size_t)node * 32 + lane];
    acc.x *= sw; acc.y *= sw; acc.z *= sw; acc.w *= sw;

    int e0 = g_rowptr[node];
    int e1 = g_rowptr[node + 1];
    for (int e = e0; e < e1; e++) {
        int2 rec = __ldg(&g_adj[e]);
        float w  = __int_as_float(rec.y);
        float4 v = hv[(size_t)rec.x * 32 + lane];
        acc.x = fmaf(v.x, w, acc.x);
        acc.y = fmaf(v.y, w, acc.y);
        acc.z = fmaf(v.z, w, acc.z);
        acc.w = fmaf(v.w, w, acc.w);
    }

    float a = *pa;
    float4 bb = ((const float4*)b)[lane];
    acc.x += bb.x; acc.y += bb.y; acc.z += bb.z; acc.w += bb.w;
    acc.x = (acc.x >= 0.0f) ? acc.x : a * acc.x;
    acc.y = (acc.y >= 0.0f) ? acc.y : a * acc.y;
    acc.z = (acc.z >= 0.0f) ? acc.z : a * acc.z;
    acc.w = (acc.w >= 0.0f) ? acc.w : a * acc.w;

    ((float4*)out)[(size_t)node * 32 + lane] = acc;
}

__global__ void k_gather64(const float* __restrict__ h,
                           const float* __restrict__ b,
                           const float* __restrict__ pa,
                           float* __restrict__ out, int n)
{
    int g    = blockIdx.x * blockDim.x + threadIdx.x;
    int node = g >> 5;
    int lane = g & 31;
    if (node >= n) return;

    const float2* hv = (const float2*)h;

    float di = g_dinv[node];
    float sw = di * di;
    float2 acc = hv[(size_t)node * 32 + lane];
    acc.x *= sw; acc.y *= sw;

    int e0 = g_rowptr[node];
    int e1 = g_rowptr[node + 1];
    for (int e = e0; e < e1; e++) {
        int2 rec = __ldg(&g_adj[e]);
        float w  = __int_as_float(rec.y);
        float2 v = hv[(size_t)rec.x * 32 + lane];
        acc.x = fmaf(v.x, w, acc.x);
        acc.y = fmaf(v.y, w, acc.y);
    }

    float a = *pa;
    float2 bb = ((const float2*)b)[lane];
    acc.x += bb.x; acc.y += bb.y;
    acc.x = (acc.x >= 0.0f) ? acc.x : a * acc.x;
    acc.y = (acc.y >= 0.0f) ? acc.y : a * acc.y;

    ((float2*)out)[(size_t)node * 32 + lane] = acc;
}

// ---------------- launch -------------------------------------------------------
extern "C" void kernel_launch(void* const* d_in, const int* in_sizes, int n_in,
                              void* d_out, int out_size)
{
    const float* x   = (const float*)d_in[0];
    const int*   ei  = (const int*)  d_in[1];
    const float* W1  = (const float*)d_in[2];
    const float* b1  = (const float*)d_in[3];
    const float* W2  = (const float*)d_in[4];
    const float* b2  = (const float*)d_in[5];
    const float* pa  = (const float*)d_in[6];
    float* out = (float*)d_out;

    const int n = in_sizes[0] / FIN;     // 50000
    const int e = in_sizes[1] / 2;       // 800000

    const int smem1 = (128 * 132 + 128 * (HDIM  + 8)) * sizeof(uint32_t); // ~134 KB
    const int smem2 = (128 * 132 + 128 * (FOUTD + 8)) * sizeof(uint32_t); // ~102 KB
    cudaFuncSetAttribute(k_gemm_tc<HDIM>,  cudaFuncAttributeMaxDynamicSharedMemorySize, smem1);
    cudaFuncSetAttribute(k_gemm_tc<FOUTD>, cudaFuncAttributeMaxDynamicSharedMemorySize, smem2);

    const int T = 256;
    float* h1 = nullptr; cudaGetSymbolAddress((void**)&h1, g_h1);
    float* z1 = nullptr; cudaGetSymbolAddress((void**)&z1, g_z1);
    float* h2 = nullptr; cudaGetSymbolAddress((void**)&h2, g_h2);

    const int nb = (n + 255) / 256;      // scan blocks (196)

    // 1) CSR build
    k_zero_deg<<<(n + T - 1) / T, T>>>(n);
    k_count   <<<(e + T - 1) / T, T>>>(ei, e);
    k_dinv    <<<(n + T - 1) / T, T>>>(n);
    k_scan_blk<<<nb, 256>>>(n);
    k_scan_mid<<<1, 256>>>(nb, n);
    k_scan_add<<<nb, 256>>>(n);
    k_fill    <<<(e + T - 1) / T, T>>>(ei, e);

    // 2) conv1
    k_gemm_tc<HDIM><<<(n + 127) / 128, 256, smem1>>>(x, W1, h1, n);
    {
        long long threads = (long long)n * 32;
        k_gather128<<<(int)((threads + T - 1) / T), T>>>(h1, b1, pa, z1, n);
    }

    // 3) conv2
    k_gemm_tc<FOUTD><<<(n + 127) / 128, 256, smem2>>>(z1, W2, h2, n);
    {
        long long threads = (long long)n * 32;
        k_gather64<<<(int)((threads + T - 1) / T), T>>>(h2, b2, pa, out, n);
    }
}

// round 5
// speedup vs baseline: 2.9747x; 1.4065x over previous
#include <cuda_runtime.h>
#include <cstdint>

// Problem constants (fixed by the dataset)
#define NNODES 50000
#define FIN    128
#define HDIM   128
#define FOUTD  64
#define NEDGES 800000

// ---------------- scratch (device globals; no allocation allowed) -------------
__device__ float g_h1  [NNODES * HDIM];
__device__ float g_z1  [NNODES * HDIM];
__device__ float g_h2  [NNODES * FOUTD];
__device__ float g_dinv[NNODES];
__device__ int   g_deg [NNODES];
__device__ int   g_rowptr[NNODES + 1];
__device__ int   g_cursor[NNODES];
__device__ int2  g_adj [NEDGES];
__device__ int   g_bsum[256];
__device__ int   g_boff[256];

// ---------------- packed f32x2 helpers ----------------------------------------
__device__ __forceinline__ void ffma2(unsigned long long& d, unsigned long long a,
                                      unsigned long long b) {
    asm("fma.rn.f32x2 %0, %1, %2, %0;" : "+l"(d) : "l"(a), "l"(b));
}
__device__ __forceinline__ unsigned long long pk(float x, float y) {
    unsigned long long r;
    asm("mov.b64 %0, {%1, %2};" : "=l"(r) : "f"(x), "f"(y));
    return r;
}
__device__ __forceinline__ float2 upk(unsigned long long v) {
    float2 r;
    asm("mov.b64 {%0, %1}, %2;" : "=f"(r.x), "=f"(r.y) : "l"(v));
    return r;
}

// ---------------- degree / CSR -------------------------------------------------
__global__ void k_zero_deg(int n) {
    int i = blockIdx.x * blockDim.x + threadIdx.x;
    if (i < n) g_deg[i] = 0;
}

__global__ void k_count(const int* __restrict__ ei, int e) {
    int i = blockIdx.x * blockDim.x + threadIdx.x;
    if (i < e) atomicAdd(&g_deg[ei[e + i]], 1);
}

// Phase 1: per-block exclusive scan + dinv
__global__ void k_scan_blk(int n) {
    __shared__ int wsum[8];
    const int tid  = threadIdx.x;
    const int i    = blockIdx.x * 256 + tid;
    const int lane = tid & 31, wid = tid >> 5;

    int v = (i < n) ? g_deg[i] : 0;
    if (i < n) g_dinv[i] = rsqrtf((float)(v + 1));  // + self loop
    int x = v;
    #pragma unroll
    for (int off = 1; off < 32; off <<= 1) {
        int y = __shfl_up_sync(0xffffffffu, x, off);
        if (lane >= off) x += y;
    }
    if (lane == 31) wsum[wid] = x;
    __syncthreads();
    if (wid == 0) {
        int w = (lane < 8) ? wsum[lane] : 0;
        #pragma unroll
        for (int off = 1; off < 8; off <<= 1) {
            int y = __shfl_up_sync(0xffffffffu, w, off);
            if (lane >= off) w += y;
        }
        if (lane < 8) wsum[lane] = w;
    }
    __syncthreads();
    int base = (wid > 0) ? wsum[wid - 1] : 0;
    if (i < n) g_rowptr[i] = base + x - v;
    if (tid == 255) g_bsum[blockIdx.x] = base + x;
}

__global__ void k_scan_mid(int nb, int n) {
    __shared__ int wsum[8];
    const int tid  = threadIdx.x;
    const int lane = tid & 31, wid = tid >> 5;

    int v = (tid < nb) ? g_bsum[tid] : 0;
    int x = v;
    #pragma unroll
    for (int off = 1; off < 32; off <<= 1) {
        int y = __shfl_up_sync(0xffffffffu, x, off);
        if (lane >= off) x += y;
    }
    if (lane == 31) wsum[wid] = x;
    __syncthreads();
    if (wid == 0) {
        int w = (lane < 8) ? wsum[lane] : 0;
        #pragma unroll
        for (int off = 1; off < 8; off <<= 1) {
            int y = __shfl_up_sync(0xffffffffu, w, off);
            if (lane >= off) w += y;
        }
        if (lane < 8) wsum[lane] = w;
    }
    __syncthreads();
    int base = (wid > 0) ? wsum[wid - 1] : 0;
    g_boff[tid] = base + x - v;
    if (tid == 255) g_rowptr[n] = base + x;
}

__global__ void k_scan_add(int n) {
    int i = blockIdx.x * 256 + threadIdx.x;
    if (i < n) {
        int v = g_rowptr[i] + g_boff[blockIdx.x];
        g_rowptr[i] = v;
        g_cursor[i] = v;
    }
}

__global__ void k_fill(const int* __restrict__ ei, int e) {
    int i = blockIdx.x * blockDim.x + threadIdx.x;
    if (i >= e) return;
    int s = ei[i];
    int d = ei[e + i];
    float nrm = g_dinv[s] * g_dinv[d];
    int pos = atomicAdd(&g_cursor[d], 1);
    g_adj[pos] = make_int2(s, __float_as_int(nrm));
}

// ---------------- packed-fp32 GEMM: Y[n,BN] = X[n,128] @ W[128,BN] ------------
// CTA tile 128 x BN, BK=16, double-buffered smem, thread tile 8x8 (split),
// accumulators held as f32x2 pairs, inner product via fma.rn.f32x2.
template<int BN>
__global__ void __launch_bounds__(2 * BN)
k_gemm_ff(const float* __restrict__ X, const float* __restrict__ W,
          float* __restrict__ Y, int n)
{
    constexpr int NT  = 2 * BN;          // 256 (BN=128) / 128 (BN=64)
    constexpr int TXN = BN / 8;          // threads along N
    constexpr int XSL = 512 / NT;        // X float4 slots per thread
    constexpr int HB  = BN / 2;
    constexpr int BMP = 132;             // Xs row stride (128 + 4)

    __shared__ float Xs[2][16][BMP];     // [k][m]
    __shared__ float Ws[2][16][BN];      // [k][c]

    const int tid  = threadIdx.x;
    const int tx   = tid & (TXN - 1);
    const int ty   = tid / TXN;          // 0..15
    const int row0 = blockIdx.x * 128;

    const float4* Xv = (const float4*)X;
    const float4* Wv = (const float4*)W;

    // ---- load chunk 0 ----
    {
        #pragma unroll
        for (int q = 0; q < XSL; q++) {
            int s = tid + q * NT;
            int r = s >> 2, kq = s & 3;
            float4 v = make_float4(0.f, 0.f, 0.f, 0.f);
            if (row0 + r < n) v = Xv[(size_t)(row0 + r) * 32 + kq];
            Xs[0][kq * 4 + 0][r] = v.x;
            Xs[0][kq * 4 + 1][r] = v.y;
            Xs[0][kq * 4 + 2][r] = v.z;
            Xs[0][kq * 4 + 3][r] = v.w;
        }
        #pragma unroll
        for (int q = 0; q < 2; q++) {
            int s = tid + q * NT;
            int k = s / (BN / 4), cq = s % (BN / 4);
            *(float4*)&Ws[0][k][cq * 4] = Wv[k * (BN / 4) + cq];
        }
    }
    __syncthreads();

    unsigned long long acc[8][4];
    #pragma unroll
    for (int i = 0; i < 8; i++)
        #pragma unroll
        for (int j = 0; j < 4; j++) acc[i][j] = 0ull;

    #pragma unroll
    for (int c = 0; c < 8; c++) {
        const int buf = c & 1;

        // prefetch next chunk into registers (LDG latency overlaps compute)
        float4 xr[XSL], wr[2];
        if (c < 7) {
            #pragma unroll
            for (int q = 0; q < XSL; q++) {
                int s = tid + q * NT;
                int r = s >> 2, kq = s & 3;
                xr[q] = make_float4(0.f, 0.f, 0.f, 0.f);
                if (row0 + r < n) xr[q] = Xv[(size_t)(row0 + r) * 32 + (c + 1) * 4 + kq];
            }
            #pragma unroll
            for (int q = 0; q < 2; q++) {
                int s = tid + q * NT;
                int k = s / (BN / 4), cq = s % (BN / 4);
                wr[q] = Wv[((c + 1) * 16 + k) * (BN / 4) + cq];
            }
        }

        // compute 16 k-iters from current buffer
        #pragma unroll
        for (int k = 0; k < 16; k++) {
            float4 a0 = *(const float4*)&Xs[buf][k][ty * 4];
            float4 a1 = *(const float4*)&Xs[buf][k][64 + ty * 4];
            float4 b0 = *(const float4*)&Ws[buf][k][tx * 4];
            float4 b1 = *(const float4*)&Ws[buf][k][HB + tx * 4];

            unsigned long long bp0 = pk(b0.x, b0.y);
            unsigned long long bp1 = pk(b0.z, b0.w);
            unsigned long long bp2 = pk(b1.x, b1.y);
            unsigned long long bp3 = pk(b1.z, b1.w);

            float ar[8] = {a0.x, a0.y, a0.z, a0.w, a1.x, a1.y, a1.z, a1.w};
            #pragma unroll
            for (int r = 0; r < 8; r++) {
                unsigned long long ap = pk(ar[r], ar[r]);
                ffma2(acc[r][0], ap, bp0);
                ffma2(acc[r][1], ap, bp1);
                ffma2(acc[r][2], ap, bp2);
                ffma2(acc[r][3], ap, bp3);
            }
        }

        // store prefetched chunk into the other buffer
        if (c < 7) {
            const int nb = buf ^ 1;
            #pragma unroll
            for (int q = 0; q < XSL; q++) {
                int s = tid + q * NT;
                int r = s >> 2, kq = s & 3;
                Xs[nb][kq * 4 + 0][r] = xr[q].x;
                Xs[nb][kq * 4 + 1][r] = xr[q].y;
                Xs[nb][kq * 4 + 2][r] = xr[q].z;
                Xs[nb][kq * 4 + 3][r] = xr[q].w;
            }
            #pragma unroll
            for (int q = 0; q < 2; q++) {
                int s = tid + q * NT;
                int k = s / (BN / 4), cq = s % (BN / 4);
                *(float4*)&Ws[nb][k][cq * 4] = wr[q];
            }
            __syncthreads();
        }
    }

    // ---- epilogue ----
    #pragma unroll
    for (int r = 0; r < 8; r++) {
        int row = row0 + ((r < 4) ? (ty * 4 + r) : (64 + ty * 4 + r - 4));
        if (row < n) {
            float2 u0 = upk(acc[r][0]);
            float2 u1 = upk(acc[r][1]);
            float2 u2 = upk(acc[r][2]);
            float2 u3 = upk(acc[r][3]);
            *(float4*)&Y[(size_t)row * BN + tx * 4]      = make_float4(u0.x, u0.y, u1.x, u1.y);
            *(float4*)&Y[(size_t)row * BN + HB + tx * 4] = make_float4(u2.x, u2.y, u3.x, u3.y);
        }
    }
}

// ---------------- gather (warp per dst node) + bias + PReLU -------------------
__global__ void k_gather128(const float* __restrict__ h,
                            const float* __restrict__ b,
                            const float* __restrict__ pa,
                            float* __restrict__ out, int n)
{
    int g    = blockIdx.x * blockDim.x + threadIdx.x;
    int node = g >> 5;
    int lane = g & 31;
    if (node >= n) return;

    const float4* hv = (const float4*)h;

    float di = g_dinv[node];
    float sw = di * di;
    float4 acc = hv[(size_t)node * 32 + lane];
    acc.x *= sw; acc.y *= sw; acc.z *= sw; acc.w *= sw;

    int e0 = g_rowptr[node];
    int e1 = g_rowptr[node + 1];
    for (int e = e0; e < e1; e++) {
        int2 rec = __ldg(&g_adj[e]);
        float w  = __int_as_float(rec.y);
        float4 v = hv[(size_t)rec.x * 32 + lane];
        acc.x = fmaf(v.x, w, acc.x);
        acc.y = fmaf(v.y, w, acc.y);
        acc.z = fmaf(v.z, w, acc.z);
        acc.w = fmaf(v.w, w, acc.w);
    }

    float a = *pa;
    float4 bb = ((const float4*)b)[lane];
    acc.x += bb.x; acc.y += bb.y; acc.z += bb.z; acc.w += bb.w;
    acc.x = (acc.x >= 0.0f) ? acc.x : a * acc.x;
    acc.y = (acc.y >= 0.0f) ? acc.y : a * acc.y;
    acc.z = (acc.z >= 0.0f) ? acc.z : a * acc.z;
    acc.w = (acc.w >= 0.0f) ? acc.w : a * acc.w;

    ((float4*)out)[(size_t)node * 32 + lane] = acc;
}

__global__ void k_gather64(const float* __restrict__ h,
                           const float* __restrict__ b,
                           const float* __restrict__ pa,
                           float* __restrict__ out, int n)
{
    int g    = blockIdx.x * blockDim.x + threadIdx.x;
    int node = g >> 5;
    int lane = g & 31;
    if (node >= n) return;

    const float2* hv = (const float2*)h;

    float di = g_dinv[node];
    float sw = di * di;
    float2 acc = hv[(size_t)node * 32 + lane];
    acc.x *= sw; acc.y *= sw;

    int e0 = g_rowptr[node];
    int e1 = g_rowptr[node + 1];
    for (int e = e0; e < e1; e++) {
        int2 rec = __ldg(&g_adj[e]);
        float w  = __int_as_float(rec.y);
        float2 v = hv[(size_t)rec.x * 32 + lane];
        acc.x = fmaf(v.x, w, acc.x);
        acc.y = fmaf(v.y, w, acc.y);
    }

    float a = *pa;
    float2 bb = ((const float2*)b)[lane];
    acc.x += bb.x; acc.y += bb.y;
    acc.x = (acc.x >= 0.0f) ? acc.x : a * acc.x;
    acc.y = (acc.y >= 0.0f) ? acc.y : a * acc.y;

    ((float2*)out)[(size_t)node * 32 + lane] = acc;
}

// ---------------- launch -------------------------------------------------------
extern "C" void kernel_launch(void* const* d_in, const int* in_sizes, int n_in,
                              void* d_out, int out_size)
{
    const float* x   = (const float*)d_in[0];
    const int*   ei  = (const int*)  d_in[1];
    const float* W1  = (const float*)d_in[2];
    const float* b1  = (const float*)d_in[3];
    const float* W2  = (const float*)d_in[4];
    const float* b2  = (const float*)d_in[5];
    const float* pa  = (const float*)d_in[6];
    float* out = (float*)d_out;

    const int n = in_sizes[0] / FIN;     // 50000
    const int e = in_sizes[1] / 2;       // 800000

    const int T = 256;
    float* h1 = nullptr; cudaGetSymbolAddress((void**)&h1, g_h1);
    float* z1 = nullptr; cudaGetSymbolAddress((void**)&z1, g_z1);
    float* h2 = nullptr; cudaGetSymbolAddress((void**)&h2, g_h2);

    const int nb = (n + 255) / 256;
    const int gblk = (n + 127) / 128;

    // Launch order: GEMM1 is the 6th launch (ncu -s 5 -c 1 captures it).
    k_zero_deg<<<(n + T - 1) / T, T>>>(n);                             // 1
    k_count   <<<(e + T - 1) / T, T>>>(ei, e);                         // 2
    k_scan_blk<<<nb, 256>>>(n);                                        // 3 (+dinv)
    k_scan_mid<<<1, 256>>>(nb, n);                                     // 4
    k_scan_add<<<nb, 256>>>(n);                                        // 5
    k_gemm_ff<HDIM><<<gblk, 2 * HDIM>>>(x, W1, h1, n);                 // 6 <- profiled
    k_fill    <<<(e + T - 1) / T, T>>>(ei, e);                         // 7
    {
        long long threads = (long long)n * 32;
        k_gather128<<<(int)((threads + T - 1) / T), T>>>(h1, b1, pa, z1, n);
    }
    k_gemm_ff<FOUTD><<<gblk, 2 * FOUTD>>>(z1, W2, h2, n);
    {
        long long threads = (long long)n * 32;
        k_gather64<<<(int)((threads + T - 1) / T), T>>>(h2, b2, pa, out, n);
    }
}

// round 6
// speedup vs baseline: 3.6533x; 1.2281x over previous
#include <cuda_runtime.h>
#include <cuda_fp16.h>
#include <cstdint>

// Problem constants (fixed by the dataset)
#define NNODES 50000
#define FIN    128
#define HDIM   128
#define FOUTD  64
#define NEDGES 800000

// ---------------- scratch (device globals; no allocation allowed) -------------
__device__ __half g_h1 [NNODES * HDIM];    // x @ W1   (fp16 for gather traffic)
__device__ float  g_z1 [NNODES * HDIM];    // prelu(agg1 + b1)  (fp32 into GEMM2)
__device__ __half g_h2 [NNODES * FOUTD];   // z1 @ W2  (fp16)
__device__ float  g_dinv[NNODES];
__device__ int    g_deg [NNODES];
__device__ int    g_rowptr[NNODES];
__device__ int    g_cursor[NNODES];
__device__ int2   g_adj [NEDGES];
__device__ int    g_total;

// ---------------- packed f32x2 helpers ----------------------------------------
__device__ __forceinline__ void ffma2(unsigned long long& d, unsigned long long a,
                                      unsigned long long b) {
    asm("fma.rn.f32x2 %0, %1, %2, %0;" : "+l"(d) : "l"(a), "l"(b));
}
__device__ __forceinline__ unsigned long long pk(float x, float y) {
    unsigned long long r;
    asm("mov.b64 %0, {%1, %2};" : "=l"(r) : "f"(x), "f"(y));
    return r;
}
__device__ __forceinline__ float2 upk(unsigned long long v) {
    float2 r;
    asm("mov.b64 {%0, %1}, %2;" : "=f"(r.x), "=f"(r.y) : "l"(v));
    return r;
}

// ---------------- degree / CSR -------------------------------------------------
__global__ void k_zero_deg(int n) {
    int i = blockIdx.x * blockDim.x + threadIdx.x;
    if (i < n) g_deg[i] = 0;
    if (i == 0) g_total = 0;
}

__global__ void k_count(const int* __restrict__ ei, int e) {
    int i = blockIdx.x * blockDim.x + threadIdx.x;
    if (i < e) atomicAdd(&g_deg[ei[e + i]], 1);
}

// Single-pass scan: per-block exclusive scan + atomic base (ranges need not be
// in node order — gather only needs a contiguous [start, start+deg) per node).
__global__ void k_scan_one(int n) {
    __shared__ int wsum[8];
    __shared__ int sbase;
    const int tid  = threadIdx.x;
    const int i    = blockIdx.x * 256 + tid;
    const int lane = tid & 31, wid = tid >> 5;

    int v = (i < n) ? g_deg[i] : 0;
    if (i < n) g_dinv[i] = rsqrtf((float)(v + 1));  // + self loop
    int x = v;
    #pragma unroll
    for (int off = 1; off < 32; off <<= 1) {
        int y = __shfl_up_sync(0xffffffffu, x, off);
        if (lane >= off) x += y;
    }
    if (lane == 31) wsum[wid] = x;
    __syncthreads();
    if (wid == 0) {
        int w = (lane < 8) ? wsum[lane] : 0;
        #pragma unroll
        for (int off = 1; off < 8; off <<= 1) {
            int y = __shfl_up_sync(0xffffffffu, w, off);
            if (lane >= off) w += y;
        }
        if (lane < 8) wsum[lane] = w;
    }
    __syncthreads();
    int base = (wid > 0) ? wsum[wid - 1] : 0;
    int excl = base + x - v;                 // block-local exclusive prefix
    if (tid == 0) sbase = atomicAdd(&g_total, wsum[7]);
    __syncthreads();
    if (i < n) {
        int p = sbase + excl;
        g_rowptr[i] = p;
        g_cursor[i] = p;
    }
}

__global__ void k_fill(const int* __restrict__ ei, int e) {
    int i = blockIdx.x * blockDim.x + threadIdx.x;
    if (i >= e) return;
    int s = ei[i];
    int d = ei[e + i];
    float nrm = g_dinv[s] * g_dinv[d];
    int pos = atomicAdd(&g_cursor[d], 1);
    g_adj[pos] = make_int2(s, __float_as_int(nrm));
}

// ---------------- packed-fp32 GEMM: Y[n,BN] = X[n,128] @ W[128,BN], Y fp16 ----
// CTA tile 128 x BN, BK=16, double-buffered smem, thread tile 8x8 (split),
// inner product via fma.rn.f32x2. Output converted to fp16 for the gather.
template<int BN>
__global__ void __launch_bounds__(2 * BN)
k_gemm_ff(const float* __restrict__ X, const float* __restrict__ W,
          __half* __restrict__ Y, int n)
{
    constexpr int NT  = 2 * BN;
    constexpr int TXN = BN / 8;
    constexpr int XSL = 512 / NT;
    constexpr int HB  = BN / 2;
    constexpr int BMP = 132;

    __shared__ float Xs[2][16][BMP];
    __shared__ float Ws[2][16][BN];

    const int tid  = threadIdx.x;
    const int tx   = tid & (TXN - 1);
    const int ty   = tid / TXN;
    const int row0 = blockIdx.x * 128;

    const float4* Xv = (const float4*)X;
    const float4* Wv = (const float4*)W;

    {
        #pragma unroll
        for (int q = 0; q < XSL; q++) {
            int s = tid + q * NT;
            int r = s >> 2, kq = s & 3;
            float4 v = make_float4(0.f, 0.f, 0.f, 0.f);
            if (row0 + r < n) v = Xv[(size_t)(row0 + r) * 32 + kq];
            Xs[0][kq * 4 + 0][r] = v.x;
            Xs[0][kq * 4 + 1][r] = v.y;
            Xs[0][kq * 4 + 2][r] = v.z;
            Xs[0][kq * 4 + 3][r] = v.w;
        }
        #pragma unroll
        for (int q = 0; q < 2; q++) {
            int s = tid + q * NT;
            int k = s / (BN / 4), cq = s % (BN / 4);
            *(float4*)&Ws[0][k][cq * 4] = Wv[k * (BN / 4) + cq];
        }
    }
    __syncthreads();

    unsigned long long acc[8][4];
    #pragma unroll
    for (int i = 0; i < 8; i++)
        #pragma unroll
        for (int j = 0; j < 4; j++) acc[i][j] = 0ull;

    #pragma unroll
    for (int c = 0; c < 8; c++) {
        const int buf = c & 1;

        float4 xr[XSL], wr[2];
        if (c < 7) {
            #pragma unroll
            for (int q = 0; q < XSL; q++) {
                int s = tid + q * NT;
                int r = s >> 2, kq = s & 3;
                xr[q] = make_float4(0.f, 0.f, 0.f, 0.f);
                if (row0 + r < n) xr[q] = Xv[(size_t)(row0 + r) * 32 + (c + 1) * 4 + kq];
            }
            #pragma unroll
            for (int q = 0; q < 2; q++) {
                int s = tid + q * NT;
                int k = s / (BN / 4), cq = s % (BN / 4);
                wr[q] = Wv[((c + 1) * 16 + k) * (BN / 4) + cq];
            }
        }

        #pragma unroll
        for (int k = 0; k < 16; k++) {
            float4 a0 = *(const float4*)&Xs[buf][k][ty * 4];
            float4 a1 = *(const float4*)&Xs[buf][k][64 + ty * 4];
            float4 b0 = *(const float4*)&Ws[buf][k][tx * 4];
            float4 b1 = *(const float4*)&Ws[buf][k][HB + tx * 4];

            unsigned long long bp0 = pk(b0.x, b0.y);
            unsigned long long bp1 = pk(b0.z, b0.w);
            unsigned long long bp2 = pk(b1.x, b1.y);
            unsigned long long bp3 = pk(b1.z, b1.w);

            float ar[8] = {a0.x, a0.y, a0.z, a0.w, a1.x, a1.y, a1.z, a1.w};
            #pragma unroll
            for (int r = 0; r < 8; r++) {
                unsigned long long ap = pk(ar[r], ar[r]);
                ffma2(acc[r][0], ap, bp0);
                ffma2(acc[r][1], ap, bp1);
                ffma2(acc[r][2], ap, bp2);
                ffma2(acc[r][3], ap, bp3);
            }
        }

        if (c < 7) {
            const int nb = buf ^ 1;
            #pragma unroll
            for (int q = 0; q < XSL; q++) {
                int s = tid + q * NT;
                int r = s >> 2, kq = s & 3;
                Xs[nb][kq * 4 + 0][r] = xr[q].x;
                Xs[nb][kq * 4 + 1][r] = xr[q].y;
                Xs[nb][kq * 4 + 2][r] = xr[q].z;
                Xs[nb][kq * 4 + 3][r] = xr[q].w;
            }
            #pragma unroll
            for (int q = 0; q < 2; q++) {
                int s = tid + q * NT;
                int k = s / (BN / 4), cq = s % (BN / 4);
                *(float4*)&Ws[nb][k][cq * 4] = wr[q];
            }
            __syncthreads();
        }
    }

    // ---- epilogue: fp32 -> fp16 ----
    #pragma unroll
    for (int r = 0; r < 8; r++) {
        int row = row0 + ((r < 4) ? (ty * 4 + r) : (64 + ty * 4 + r - 4));
        if (row < n) {
            float2 u0 = upk(acc[r][0]);
            float2 u1 = upk(acc[r][1]);
            float2 u2 = upk(acc[r][2]);
            float2 u3 = upk(acc[r][3]);
            __half2 p0 = __floats2half2_rn(u0.x, u0.y);
            __half2 p1 = __floats2half2_rn(u1.x, u1.y);
            __half2 p2 = __floats2half2_rn(u2.x, u2.y);
            __half2 p3 = __floats2half2_rn(u3.x, u3.y);
            uint2 s0 = make_uint2(*(uint32_t*)&p0, *(uint32_t*)&p1);
            uint2 s1 = make_uint2(*(uint32_t*)&p2, *(uint32_t*)&p3);
            *(uint2*)&Y[(size_t)row * BN + tx * 4]      = s0;
            *(uint2*)&Y[(size_t)row * BN + HB + tx * 4] = s1;
        }
    }
}

// ---------------- gather (warp per dst node) + bias + PReLU -------------------
// conv1: h fp16 [N,128] (256B/row), out z1 fp32
__global__ void k_gather128(const __half* __restrict__ h,
                            const float* __restrict__ b,
                            const float* __restrict__ pa,
                            float* __restrict__ out, int n)
{
    int g    = blockIdx.x * blockDim.x + threadIdx.x;
    int node = g >> 5;
    int lane = g & 31;
    if (node >= n) return;

    const uint2* hv = (const uint2*)h;   // 8 B = 4 halves per lane

    float di = g_dinv[node];
    float sw = di * di;
    uint2 raw = hv[(size_t)node * 32 + lane];
    float2 f0 = __half22float2(*(__half2*)&raw.x);
    float2 f1 = __half22float2(*(__half2*)&raw.y);
    float4 acc = make_float4(f0.x * sw, f0.y * sw, f1.x * sw, f1.y * sw);

    int e0 = g_rowptr[node];
    int e1 = e0 + g_deg[node];
    for (int e = e0; e < e1; e++) {
        int2 rec = __ldg(&g_adj[e]);
        float w  = __int_as_float(rec.y);
        uint2 rv = hv[(size_t)rec.x * 32 + lane];
        float2 v0 = __half22float2(*(__half2*)&rv.x);
        float2 v1 = __half22float2(*(__half2*)&rv.y);
        acc.x = fmaf(v0.x, w, acc.x);
        acc.y = fmaf(v0.y, w, acc.y);
        acc.z = fmaf(v1.x, w, acc.z);
        acc.w = fmaf(v1.y, w, acc.w);
    }

    float a = *pa;
    float4 bb = ((const float4*)b)[lane];
    acc.x += bb.x; acc.y += bb.y; acc.z += bb.z; acc.w += bb.w;
    acc.x = (acc.x >= 0.0f) ? acc.x : a * acc.x;
    acc.y = (acc.y >= 0.0f) ? acc.y : a * acc.y;
    acc.z = (acc.z >= 0.0f) ? acc.z : a * acc.z;
    acc.w = (acc.w >= 0.0f) ? acc.w : a * acc.w;

    ((float4*)out)[(size_t)node * 32 + lane] = acc;
}

// conv2: h fp16 [N,64] (128B/row), out fp32 -> d_out
__global__ void k_gather64(const __half* __restrict__ h,
                           const float* __restrict__ b,
                           const float* __restrict__ pa,
                           float* __restrict__ out, int n)
{
    int g    = blockIdx.x * blockDim.x + threadIdx.x;
    int node = g >> 5;
    int lane = g & 31;
    if (node >= n) return;

    const __half2* hv = (const __half2*)h;   // 4 B = 2 halves per lane

    float di = g_dinv[node];
    float sw = di * di;
    float2 f = __half22float2(hv[(size_t)node * 32 + lane]);
    float2 acc = make_float2(f.x * sw, f.y * sw);

    int e0 = g_rowptr[node];
    int e1 = e0 + g_deg[node];
    for (int e = e0; e < e1; e++) {
        int2 rec = __ldg(&g_adj[e]);
        float w  = __int_as_float(rec.y);
        float2 v = __half22float2(hv[(size_t)rec.x * 32 + lane]);
        acc.x = fmaf(v.x, w, acc.x);
        acc.y = fmaf(v.y, w, acc.y);
    }

    float a = *pa;
    float2 bb = ((const float2*)b)[lane];
    acc.x += bb.x; acc.y += bb.y;
    acc.x = (acc.x >= 0.0f) ? acc.x : a * acc.x;
    acc.y = (acc.y >= 0.0f) ? acc.y : a * acc.y;

    ((float2*)out)[(size_t)node * 32 + lane] = acc;
}

// ---------------- launch -------------------------------------------------------
extern "C" void kernel_launch(void* const* d_in, const int* in_sizes, int n_in,
                              void* d_out, int out_size)
{
    const float* x   = (const float*)d_in[0];
    const int*   ei  = (const int*)  d_in[1];
    const float* W1  = (const float*)d_in[2];
    const float* b1  = (const float*)d_in[3];
    const float* W2  = (const float*)d_in[4];
    const float* b2  = (const float*)d_in[5];
    const float* pa  = (const float*)d_in[6];
    float* out = (float*)d_out;

    const int n = in_sizes[0] / FIN;     // 50000
    const int e = in_sizes[1] / 2;       // 800000

    const int T = 256;
    __half* h1 = nullptr; cudaGetSymbolAddress((void**)&h1, g_h1);
    float*  z1 = nullptr; cudaGetSymbolAddress((void**)&z1, g_z1);
    __half* h2 = nullptr; cudaGetSymbolAddress((void**)&h2, g_h2);

    const int nb   = (n + 255) / 256;
    const int gblk = (n + 127) / 128;

    // Launch order: k_gather128 is the 6th launch (ncu -s 5 -c 1 captures it).
    k_zero_deg<<<(n + T - 1) / T, T>>>(n);                             // 1
    k_count   <<<(e + T - 1) / T, T>>>(ei, e);                         // 2
    k_scan_one<<<nb, 256>>>(n);                                        // 3 (+dinv)
    k_gemm_ff<HDIM><<<gblk, 2 * HDIM>>>(x, W1, h1, n);                 // 4
    k_fill    <<<(e + T - 1) / T, T>>>(ei, e);                         // 5
    {
        long long threads = (long long)n * 32;
        k_gather128<<<(int)((threads + T - 1) / T), T>>>(h1, b1, pa, z1, n);  // 6 <- profiled
    }
    k_gemm_ff<FOUTD><<<gblk, 2 * FOUTD>>>(z1, W2, h2, n);
    {
        long long threads = (long long)n * 32;
        k_gather64<<<(int)((threads + T - 1) / T), T>>>(h2, b2, pa, out, n);
    }
}